// round 1
// baseline (speedup 1.0000x reference)
#include <cuda_runtime.h>
#include <cuda_bf16.h>

#define NN 4096
#define FD 128
#define MAXNBR 128

// Scratch (device globals; no cudaMalloc allowed)
__device__ float g_S[(size_t)NN * NN];   // 64 MB: S = exp(f^T C f)
__device__ float g_T[(size_t)NN * NN];   // 64 MB: T = out^T = S_row / D_row
__device__ int   g_idx[(size_t)NN * MAXNBR];
__device__ int   g_cnt[NN];

// ---------------------------------------------------------------------------
// Kernel 0: build padded neighbor lists (CSR-ish) from dense binary adjacency
// ---------------------------------------------------------------------------
__global__ void build_nbr_kernel(const float* __restrict__ nbr) {
    __shared__ int s_cnt;
    const int j = blockIdx.x;
    if (threadIdx.x == 0) s_cnt = 0;
    __syncthreads();
    const float* row = nbr + (size_t)j * NN;
    for (int c = threadIdx.x; c < NN; c += blockDim.x) {
        if (row[c] != 0.0f) {
            int p = atomicAdd(&s_cnt, 1);
            if (p < MAXNBR) g_idx[(size_t)j * MAXNBR + p] = c;
        }
    }
    __syncthreads();
    if (threadIdx.x == 0) g_cnt[j] = min(s_cnt, MAXNBR);
}

// ---------------------------------------------------------------------------
// Kernel 1: S = exp(f^T diag(wq*wk) f)  — symmetric, compute upper-tri tiles
// 64x64 tile per CTA, 256 threads, 4x4 per thread, K=128 in two 64-chunks.
// ---------------------------------------------------------------------------
__global__ void compute_S_kernel(const float* __restrict__ f,
                                 const float* __restrict__ wq,
                                 const float* __restrict__ wk) {
    const int ti = blockIdx.y;
    const int tj = blockIdx.x;
    if (tj < ti) return;  // upper triangle only (mirror written below)

    __shared__ float smem[2 * 64 * 64];   // As | Bs  (32 KB)
    __shared__ float cs[FD];
    float* As = smem;            // As[d2*64 + i_local] = c[d]*f[d][i0+i_local]
    float* Bs = smem + 64 * 64;  // Bs[d2*64 + j_local] = f[d][j0+j_local]

    const int tid = threadIdx.x;          // 0..255
    const int tx = tid & 15;
    const int ty = tid >> 4;
    const int i0 = ti * 64;
    const int j0 = tj * 64;

    if (tid < FD) cs[tid] = wq[tid] * wk[tid];
    __syncthreads();

    float acc[4][4] = {};

    #pragma unroll
    for (int kb = 0; kb < 2; ++kb) {
        // load 64 d-slices of A and B tiles (coalesced: 64 consecutive cols)
        #pragma unroll
        for (int r = 0; r < 16; ++r) {
            int e = tid + r * 256;          // 0..4095
            int d2 = e >> 6;
            int c  = e & 63;
            int d  = kb * 64 + d2;
            As[e] = cs[d] * f[(size_t)d * NN + i0 + c];
            Bs[e] = f[(size_t)d * NN + j0 + c];
        }
        __syncthreads();

        #pragma unroll 16
        for (int d2 = 0; d2 < 64; ++d2) {
            float4 a = *(const float4*)&As[d2 * 64 + ty * 4];
            float4 b = *(const float4*)&Bs[d2 * 64 + tx * 4];
            acc[0][0] += a.x * b.x; acc[0][1] += a.x * b.y; acc[0][2] += a.x * b.z; acc[0][3] += a.x * b.w;
            acc[1][0] += a.y * b.x; acc[1][1] += a.y * b.y; acc[1][2] += a.y * b.z; acc[1][3] += a.y * b.w;
            acc[2][0] += a.z * b.x; acc[2][1] += a.z * b.y; acc[2][2] += a.z * b.z; acc[2][3] += a.z * b.w;
            acc[3][0] += a.w * b.x; acc[3][1] += a.w * b.y; acc[3][2] += a.w * b.z; acc[3][3] += a.w * b.w;
        }
        __syncthreads();
    }

    float ev[4][4];
    #pragma unroll
    for (int r = 0; r < 4; ++r)
        #pragma unroll
        for (int c = 0; c < 4; ++c)
            ev[r][c] = __expf(acc[r][c]);

    // primary tile write: rows i0+ty*4+r, cols j0+tx*4.. (coalesced float4)
    #pragma unroll
    for (int r = 0; r < 4; ++r) {
        float4 w = make_float4(ev[r][0], ev[r][1], ev[r][2], ev[r][3]);
        *(float4*)&g_S[(size_t)(i0 + ty * 4 + r) * NN + j0 + tx * 4] = w;
    }

    // mirror tile via smem transpose staging (skip diagonal: identical region)
    if (ti != tj) {
        float* st = smem;  // [64][68] = 17.4 KB, reuse As/Bs
        #pragma unroll
        for (int r = 0; r < 4; ++r)
            #pragma unroll
            for (int c = 0; c < 4; ++c)
                st[(tx * 4 + c) * 68 + (ty * 4 + r)] = ev[r][c];
        __syncthreads();
        #pragma unroll
        for (int r = 0; r < 4; ++r) {
            int jl = ty * 4 + r;
            float4 w = *(const float4*)&st[jl * 68 + tx * 4];
            *(float4*)&g_S[(size_t)(j0 + jl) * NN + i0 + tx * 4] = w;
        }
    }
}

// ---------------------------------------------------------------------------
// Kernel 2: per row j: D[j,:] = sum_{k in nbr(j)} S[k,:];  T[j,:] = S[j,:]/D[j,:]
// (T = out^T since S is symmetric). One CTA per j, 256 threads x 4 float4 cols.
// ---------------------------------------------------------------------------
__global__ void compute_T_kernel() {
    const int j = blockIdx.x;
    __shared__ int s_idx[MAXNBR];
    __shared__ int s_cnt;
    const int tid = threadIdx.x;  // 0..255

    if (tid == 0) s_cnt = g_cnt[j];
    if (tid < MAXNBR) s_idx[tid] = g_idx[(size_t)j * MAXNBR + tid];
    __syncthreads();
    const int cnt = s_cnt;

    float4 a0 = make_float4(0.f, 0.f, 0.f, 0.f);
    float4 a1 = a0, a2 = a0, a3 = a0;

    for (int k = 0; k < cnt; ++k) {
        const float4* srow = (const float4*)(g_S + (size_t)s_idx[k] * NN);
        float4 v0 = srow[tid];
        float4 v1 = srow[tid + 256];
        float4 v2 = srow[tid + 512];
        float4 v3 = srow[tid + 768];
        a0.x += v0.x; a0.y += v0.y; a0.z += v0.z; a0.w += v0.w;
        a1.x += v1.x; a1.y += v1.y; a1.z += v1.z; a1.w += v1.w;
        a2.x += v2.x; a2.y += v2.y; a2.z += v2.z; a2.w += v2.w;
        a3.x += v3.x; a3.y += v3.y; a3.z += v3.z; a3.w += v3.w;
    }

    const float4* sj = (const float4*)(g_S + (size_t)j * NN);
    float4* tj = (float4*)(g_T + (size_t)j * NN);
    float4 s0 = sj[tid], s1 = sj[tid + 256], s2 = sj[tid + 512], s3 = sj[tid + 768];
    tj[tid]       = make_float4(s0.x / a0.x, s0.y / a0.y, s0.z / a0.z, s0.w / a0.w);
    tj[tid + 256] = make_float4(s1.x / a1.x, s1.y / a1.y, s1.z / a1.z, s1.w / a1.w);
    tj[tid + 512] = make_float4(s2.x / a2.x, s2.y / a2.y, s2.z / a2.z, s2.w / a2.w);
    tj[tid + 768] = make_float4(s3.x / a3.x, s3.y / a3.y, s3.z / a3.z, s3.w / a3.w);
}

// ---------------------------------------------------------------------------
// Kernel 3: out = T^T (32x32 smem tile transpose)
// ---------------------------------------------------------------------------
__global__ void transpose_kernel(float* __restrict__ out) {
    __shared__ float tile[32][33];
    const int bx = blockIdx.x, by = blockIdx.y;
    const int x = bx * 32 + threadIdx.x;
    const int y0 = by * 32;
    #pragma unroll
    for (int r = threadIdx.y; r < 32; r += 8)
        tile[r][threadIdx.x] = g_T[(size_t)(y0 + r) * NN + x];
    __syncthreads();
    const int xo = by * 32 + threadIdx.x;
    const int yo0 = bx * 32;
    #pragma unroll
    for (int r = threadIdx.y; r < 32; r += 8)
        out[(size_t)(yo0 + r) * NN + xo] = tile[threadIdx.x][r];
}

// ---------------------------------------------------------------------------
extern "C" void kernel_launch(void* const* d_in, const int* in_sizes, int n_in,
                              void* d_out, int out_size) {
    const float* f   = (const float*)d_in[0];   // [128, 4096]
    const float* nbr = (const float*)d_in[1];   // [4096, 4096]
    const float* wq  = (const float*)d_in[2];   // [128]
    const float* wk  = (const float*)d_in[3];   // [128]
    float* out = (float*)d_out;                 // [4096, 4096]

    build_nbr_kernel<<<NN, 256>>>(nbr);
    compute_S_kernel<<<dim3(64, 64), 256>>>(f, wq, wk);
    compute_T_kernel<<<NN, 256>>>();
    transpose_kernel<<<dim3(NN / 32, NN / 32), dim3(32, 8)>>>(out);
}